// round 6
// baseline (speedup 1.0000x reference)
#include <cuda_runtime.h>
#include <math.h>

#define N_NODES 50000
#define E_MAX   800000
#define D_H 64

// Scratch (device globals -- no allocation allowed)
__device__ float g_p[N_NODES * D_H];      // x @ Wl
__device__ float g_base[N_NODES * D_H];   // x @ Wr + bl
__device__ float g_h[N_NODES * D_H];      // elu(...) -> next layer input
__device__ int   g_cnt[N_NODES];
__device__ float g_inv[N_NODES];
__device__ int   g_row[N_NODES + 1];      // CSR row offsets (by dst)
__device__ int   g_cursor[N_NODES];
__device__ int   g_csr[E_MAX];            // src indices grouped by dst
__device__ int   g_src[E_MAX];
__device__ int   g_dst[E_MAX];
__device__ float4 g_a[N_NODES];           // h @ Wp_top + bp
__device__ float4 g_b[N_NODES];           // h @ Wp_bot

// packed fp32x2 FMA (sm_100+): d = a * b + c elementwise on (lo,hi) pairs.
__device__ __forceinline__ unsigned long long ffma2(
        unsigned long long a, unsigned long long b, unsigned long long c) {
    unsigned long long d;
    asm("fma.rn.f32x2 %0, %1, %2, %3;" : "=l"(d) : "l"(a), "l"(b), "l"(c));
    return d;
}

__global__ void zero_cnt_kernel() {
    int i = blockIdx.x * blockDim.x + threadIdx.x;
    if (i < N_NODES) g_cnt[i] = 0;
}

// decode src/dst (+ count degrees) in one pass. int64-vs-int32 detection is
// done per block from the first 128 words (all L2-broadcast): for int64
// indices < 2^31 every odd word is 0; for 64 random int32 indices it isn't.
__global__ void convert_count_kernel(const int* __restrict__ w, int E) {
    __shared__ int is64_s;
    if (threadIdx.x == 0) {
        int z = 1;
        for (int i = 1; i < 129; i += 2)
            if (w[i] != 0) { z = 0; break; }
        is64_s = z;
    }
    __syncthreads();
    int is64 = is64_s;
    int e = blockIdx.x * blockDim.x + threadIdx.x;
    if (e >= E) return;
    int s, d;
    if (is64) { s = w[2 * e]; d = w[2 * (E + e)]; }
    else      { s = w[e];     d = w[E + e]; }
    g_src[e] = s;
    g_dst[e] = d;
    atomicAdd(&g_cnt[d], 1);
}

// Single block, 1024 threads: exclusive scan of g_cnt -> g_row, g_cursor, g_inv
__global__ void scan_kernel() {
    __shared__ int sums[1024];
    int t = threadIdx.x;
    const int CH = (N_NODES + 1023) / 1024;
    int begin = t * CH;
    int end = begin + CH; if (end > N_NODES) end = N_NODES;
    int s = 0;
    for (int i = begin; i < end; i++) s += g_cnt[i];
    sums[t] = s;
    __syncthreads();
    for (int off = 1; off < 1024; off <<= 1) {
        int v = (t >= off) ? sums[t - off] : 0;
        __syncthreads();
        sums[t] += v;
        __syncthreads();
    }
    int run = (t == 0) ? 0 : sums[t - 1];
    for (int i = begin; i < end; i++) {
        g_row[i] = run;
        g_cursor[i] = run;
        int c = g_cnt[i];
        run += c;
        g_inv[i] = 1.0f / (float)(c > 1 ? c : 1);
    }
    if (t == 1023) g_row[N_NODES] = run;
}

__global__ void fill_kernel(int E) {
    int e = blockIdx.x * blockDim.x + threadIdx.x;
    if (e < E) {
        int pos = atomicAdd(&g_cursor[g_dst[e]], 1);
        g_csr[pos] = g_src[e];
    }
}

// Fused dual GEMM: P = X @ Wl ; BASE = X @ Wr + bl.
// Block computes 64 rows x 128 combined cols (0-63 -> P, 64-127 -> BASE).
// 128 threads, 8x8 register tile each, computed as 8x4 packed f32x2 pairs.
// Xs2 holds X values DUPLICATED ((x,x) pairs) so the broadcast operand of
// fma.rn.f32x2 is a direct 64-bit shared load -- no packing instructions.
// Per k-step: 6 LDS.128 + 32 FFMA2 = 38 issue slots for 64 lane-FMAs.
__global__ void __launch_bounds__(128) gemm2_kernel(
        const float* __restrict__ X,
        const float* __restrict__ Wl, const float* __restrict__ Wr,
        const float* __restrict__ bl,
        float* __restrict__ P, float* __restrict__ BASE,
        int N, int K) {
    __shared__ float Xs2[16][128];   // duplicated pairs: Xs2[k][2r]=Xs2[k][2r+1]=X[r]
    __shared__ float Ws[16][128];
    int tid = threadIdx.x;
    int tx = tid & 15;       // col group (8 cols = 4 pairs)
    int ty = tid >> 4;       // row group (8 rows)
    int row0 = blockIdx.x * 64;

    unsigned long long acc[8][4];
#pragma unroll
    for (int i = 0; i < 8; i++)
#pragma unroll
        for (int j = 0; j < 4; j++) acc[i][j] = 0ull;

    for (int k0 = 0; k0 < K; k0 += 16) {
        // stage X tile (64 rows x 16 k), transposed + duplicated
#pragma unroll
        for (int i = 0; i < 2; i++) {
            int f = tid + i * 128;       // 0..255 float4 slots
            int r = f >> 2;              // 0..63
            int kq = (f & 3) * 4;        // 0,4,8,12
            int grow = row0 + r;
            float4 v = make_float4(0.f, 0.f, 0.f, 0.f);
            if (grow < N) v = *(const float4*)(X + (long)grow * K + k0 + kq);
            *(float2*)&Xs2[kq + 0][2 * r] = make_float2(v.x, v.x);
            *(float2*)&Xs2[kq + 1][2 * r] = make_float2(v.y, v.y);
            *(float2*)&Xs2[kq + 2][2 * r] = make_float2(v.z, v.z);
            *(float2*)&Xs2[kq + 3][2 * r] = make_float2(v.w, v.w);
        }
        // stage combined W tile (16 k x 128 cols)
#pragma unroll
        for (int i = 0; i < 4; i++) {
            int f = tid + i * 128;       // 0..511 float4 slots
            int k = f >> 5;
            int c0 = (f & 31) * 4;
            const float* src = (c0 < 64) ? (Wl + (k0 + k) * 64 + c0)
                                         : (Wr + (k0 + k) * 64 + c0 - 64);
            *(float4*)&Ws[k][c0] = *(const float4*)src;
        }
        __syncthreads();
#pragma unroll
        for (int kk = 0; kk < 16; kk++) {
            // a: 8 duplicated row-pairs (64-bit each) via 4x LDS.128
            ulonglong2 av0 = *(const ulonglong2*)&Xs2[kk][ty * 16 + 0];
            ulonglong2 av1 = *(const ulonglong2*)&Xs2[kk][ty * 16 + 4];
            ulonglong2 av2 = *(const ulonglong2*)&Xs2[kk][ty * 16 + 8];
            ulonglong2 av3 = *(const ulonglong2*)&Xs2[kk][ty * 16 + 12];
            // b: 4 col-pairs via 2x LDS.128
            ulonglong2 bv0 = *(const ulonglong2*)&Ws[kk][tx * 8 + 0];
            ulonglong2 bv1 = *(const ulonglong2*)&Ws[kk][tx * 8 + 4];
            unsigned long long a[8] = {av0.x, av0.y, av1.x, av1.y,
                                       av2.x, av2.y, av3.x, av3.y};
            unsigned long long b[4] = {bv0.x, bv0.y, bv1.x, bv1.y};
#pragma unroll
            for (int i = 0; i < 8; i++)
#pragma unroll
                for (int j = 0; j < 4; j++)
                    acc[i][j] = ffma2(a[i], b[j], acc[i][j]);
        }
        __syncthreads();
    }

    bool isP = (tx < 8);
    int c0 = (isP ? tx : tx - 8) * 8;
    float bias[8];
#pragma unroll
    for (int j = 0; j < 8; j++) bias[j] = isP ? 0.0f : bl[c0 + j];
    float* dstbuf = isP ? P : BASE;
#pragma unroll
    for (int i = 0; i < 8; i++) {
        int grow = row0 + ty * 8 + i;
        if (grow < N) {
            float2 f0 = *(float2*)&acc[i][0];
            float2 f1 = *(float2*)&acc[i][1];
            float2 f2 = *(float2*)&acc[i][2];
            float2 f3 = *(float2*)&acc[i][3];
            float4* o = (float4*)(dstbuf + grow * 64 + c0);
            o[0] = make_float4(f0.x + bias[0], f0.y + bias[1],
                               f1.x + bias[2], f1.y + bias[3]);
            o[1] = make_float4(f2.x + bias[4], f2.y + bias[5],
                               f3.x + bias[6], f3.y + bias[7]);
        }
    }
}

// h[i] = elu(base[i] + inv[i] * sum_{j in N(i)} p[j]) — one warp per node,
// lane handles 2 floats (float2), neighbor rows read coalesced (256B/row).
// PROJ: additionally a[i] = h[i]@Wp_top + bp, b[i] = h[i]@Wp_bot via warp
// shuffle reduction (Wp staged in shared).
template <bool PROJ>
__global__ void gather_elu_kernel(const float* __restrict__ Wp,
                                  const float* __restrict__ bp) {
    __shared__ float Ws[512];
    if (PROJ) {
        for (int i = threadIdx.x; i < 512; i += blockDim.x) Ws[i] = Wp[i];
        __syncthreads();
    }
    int w = (blockIdx.x * blockDim.x + threadIdx.x) >> 5;
    if (w >= N_NODES) return;
    int lane = threadIdx.x & 31;
    int beg = g_row[w], end = g_row[w + 1];

    const float2* P = (const float2*)g_p;
    float ax = 0.0f, ay = 0.0f;
    int j = beg;
    for (; j + 1 < end; j += 2) {
        int s0 = g_csr[j], s1 = g_csr[j + 1];
        float2 v0 = P[s0 * 32 + lane];
        float2 v1 = P[s1 * 32 + lane];
        ax += v0.x + v1.x;
        ay += v0.y + v1.y;
    }
    if (j < end) {
        float2 v = P[g_csr[j] * 32 + lane];
        ax += v.x; ay += v.y;
    }
    float inv = g_inv[w];
    float2 b = ((const float2*)g_base)[w * 32 + lane];
    float vx = b.x + inv * ax;
    float vy = b.y + inv * ay;
    vx = vx > 0.0f ? vx : expm1f(vx);
    vy = vy > 0.0f ? vy : expm1f(vy);
    ((float2*)g_h)[w * 32 + lane] = make_float2(vx, vy);

    if (PROJ) {
        int c0 = 2 * lane;
        float sa[4], sb[4];
#pragma unroll
        for (int o = 0; o < 4; o++) {
            sa[o] = vx * Ws[c0 * 4 + o]        + vy * Ws[(c0 + 1) * 4 + o];
            sb[o] = vx * Ws[(64 + c0) * 4 + o] + vy * Ws[(64 + c0 + 1) * 4 + o];
        }
#pragma unroll
        for (int off = 16; off > 0; off >>= 1) {
#pragma unroll
            for (int o = 0; o < 4; o++) {
                sa[o] += __shfl_xor_sync(0xffffffffu, sa[o], off);
                sb[o] += __shfl_xor_sync(0xffffffffu, sb[o], off);
            }
        }
        if (lane == 0) {
            g_a[w] = make_float4(sa[0] + bp[0], sa[1] + bp[1],
                                 sa[2] + bp[2], sa[3] + bp[3]);
            g_b[w] = make_float4(sb[0], sb[1], sb[2], sb[3]);
        }
    }
}

// out[e] = a[src] + b[dst]
__global__ void edge_out_kernel(float* __restrict__ out, int E) {
    int e = blockIdx.x * blockDim.x + threadIdx.x;
    if (e >= E) return;
    float4 a = g_a[g_src[e]];
    float4 b = g_b[g_dst[e]];
    ((float4*)out)[e] = make_float4(a.x + b.x, a.y + b.y, a.z + b.z, a.w + b.w);
}

extern "C" void kernel_launch(void* const* d_in, const int* in_sizes, int n_in,
                              void* d_out, int out_size) {
    const float* x   = (const float*)d_in[0];
    const int*   eiw = (const int*)d_in[1];   // raw words; dtype probed on device
    const float* Wl1 = (const float*)d_in[2];
    const float* bl1 = (const float*)d_in[3];
    const float* Wr1 = (const float*)d_in[4];
    const float* Wl2 = (const float*)d_in[5];
    const float* bl2 = (const float*)d_in[6];
    const float* Wr2 = (const float*)d_in[7];
    const float* Wl3 = (const float*)d_in[8];
    const float* bl3 = (const float*)d_in[9];
    const float* Wr3 = (const float*)d_in[10];
    const float* Wp  = (const float*)d_in[11];
    const float* bp  = (const float*)d_in[12];
    float* out = (float*)d_out;

    int E = in_sizes[1] / 2;
    if (E > E_MAX) E = E_MAX;

    float* d_p;    cudaGetSymbolAddress((void**)&d_p,    g_p);
    float* d_base; cudaGetSymbolAddress((void**)&d_base, g_base);
    float* d_h;    cudaGetSymbolAddress((void**)&d_h,    g_h);

    const int TB = 256;
    int gN    = (N_NODES + TB - 1) / TB;
    int gE    = (E + TB - 1) / TB;
    int gGath = (N_NODES * 32 + TB - 1) / TB;      // 1 warp per node
    int gGemm = (N_NODES + 63) / 64;               // 64 rows per block

    // Decode edge_index + build CSR (by dst) + inverse degree
    zero_cnt_kernel<<<gN, TB>>>();
    convert_count_kernel<<<gE, TB>>>(eiw, E);
    scan_kernel<<<1, 1024>>>();
    fill_kernel<<<gE, TB>>>(E);

    // Layer 1 (K=128)
    gemm2_kernel<<<gGemm, 128>>>(x, Wl1, Wr1, bl1, d_p, d_base, N_NODES, 128);
    gather_elu_kernel<false><<<gGath, TB>>>(nullptr, nullptr);

    // Layer 2 (K=64)
    gemm2_kernel<<<gGemm, 128>>>(d_h, Wl2, Wr2, bl2, d_p, d_base, N_NODES, 64);
    gather_elu_kernel<false><<<gGath, TB>>>(nullptr, nullptr);

    // Layer 3 (K=64) + fused edge-MLP projection
    gemm2_kernel<<<gGemm, 128>>>(d_h, Wl3, Wr3, bl3, d_p, d_base, N_NODES, 64);
    gather_elu_kernel<true><<<gGath, TB>>>(Wp, bp);

    // out[e] = a[src] + b[dst]
    edge_out_kernel<<<gE, TB>>>(out, E);
}

// round 7
// speedup vs baseline: 1.0052x; 1.0052x over previous
#include <cuda_runtime.h>
#include <math.h>

#define N_NODES 50000
#define E_MAX   800000
#define D_H 64

// Scratch (device globals -- no allocation allowed)
__device__ float g_p[N_NODES * D_H];      // x @ Wl
__device__ float g_base[N_NODES * D_H];   // x @ Wr + bl
__device__ float g_h[N_NODES * D_H];      // elu(...) -> next layer input
__device__ int   g_cnt[N_NODES];
__device__ float g_inv[N_NODES];
__device__ int   g_row[N_NODES + 1];      // CSR row offsets (by dst)
__device__ int   g_cursor[N_NODES];
__device__ int   g_csr[E_MAX];            // src indices grouped by dst
__device__ int   g_src[E_MAX];
__device__ int   g_dst[E_MAX];
__device__ float4 g_a[N_NODES];           // h @ Wp_top + bp
__device__ float4 g_b[N_NODES];           // h @ Wp_bot

__global__ void zero_cnt_kernel() {
    int i = blockIdx.x * blockDim.x + threadIdx.x;
    if (i < N_NODES) g_cnt[i] = 0;
}

// decode src/dst (+ count degrees) in one pass. int64-vs-int32 detection is
// done per block from the first 128 words (all L2-broadcast): for int64
// indices < 2^31 every odd word is 0; for 64 random int32 indices it isn't.
__global__ void convert_count_kernel(const int* __restrict__ w, int E) {
    __shared__ int is64_s;
    if (threadIdx.x == 0) {
        int z = 1;
        for (int i = 1; i < 129; i += 2)
            if (w[i] != 0) { z = 0; break; }
        is64_s = z;
    }
    __syncthreads();
    int is64 = is64_s;
    int e = blockIdx.x * blockDim.x + threadIdx.x;
    if (e >= E) return;
    int s, d;
    if (is64) { s = w[2 * e]; d = w[2 * (E + e)]; }
    else      { s = w[e];     d = w[E + e]; }
    g_src[e] = s;
    g_dst[e] = d;
    atomicAdd(&g_cnt[d], 1);
}

// Single block, 1024 threads: exclusive scan of g_cnt -> g_row, g_cursor, g_inv
__global__ void scan_kernel() {
    __shared__ int sums[1024];
    int t = threadIdx.x;
    const int CH = (N_NODES + 1023) / 1024;
    int begin = t * CH;
    int end = begin + CH; if (end > N_NODES) end = N_NODES;
    int s = 0;
    for (int i = begin; i < end; i++) s += g_cnt[i];
    sums[t] = s;
    __syncthreads();
    for (int off = 1; off < 1024; off <<= 1) {
        int v = (t >= off) ? sums[t - off] : 0;
        __syncthreads();
        sums[t] += v;
        __syncthreads();
    }
    int run = (t == 0) ? 0 : sums[t - 1];
    for (int i = begin; i < end; i++) {
        g_row[i] = run;
        g_cursor[i] = run;
        int c = g_cnt[i];
        run += c;
        g_inv[i] = 1.0f / (float)(c > 1 ? c : 1);
    }
    if (t == 1023) g_row[N_NODES] = run;
}

__global__ void fill_kernel(int E) {
    int e = blockIdx.x * blockDim.x + threadIdx.x;
    if (e < E) {
        int pos = atomicAdd(&g_cursor[g_dst[e]], 1);
        g_csr[pos] = g_src[e];
    }
}

// Fused dual GEMM: P = X @ Wl ; BASE = X @ Wr + bl.  (R5 version)
// Block computes 64 rows x 128 combined cols (0-63 -> P, 64-127 -> BASE).
// 128 threads, 8x8 register tile each: 4x LDS.128 per k feeds 64 FMA.
__global__ void __launch_bounds__(128) gemm2_kernel(
        const float* __restrict__ X,
        const float* __restrict__ Wl, const float* __restrict__ Wr,
        const float* __restrict__ bl,
        float* __restrict__ P, float* __restrict__ BASE,
        int N, int K) {
    __shared__ float Xs[16][64];
    __shared__ float Ws[16][128];
    int tid = threadIdx.x;
    int tx = tid & 15;       // col group (8 cols)
    int ty = tid >> 4;       // row group (8 rows)
    int row0 = blockIdx.x * 64;

    float acc[8][8];
#pragma unroll
    for (int i = 0; i < 8; i++)
#pragma unroll
        for (int j = 0; j < 8; j++) acc[i][j] = 0.0f;

    for (int k0 = 0; k0 < K; k0 += 16) {
#pragma unroll
        for (int i = 0; i < 2; i++) {
            int f = tid + i * 128;
            int r = f >> 2;
            int kq = (f & 3) * 4;
            int grow = row0 + r;
            float4 v = make_float4(0.f, 0.f, 0.f, 0.f);
            if (grow < N) v = *(const float4*)(X + (long)grow * K + k0 + kq);
            Xs[kq + 0][r] = v.x; Xs[kq + 1][r] = v.y;
            Xs[kq + 2][r] = v.z; Xs[kq + 3][r] = v.w;
        }
#pragma unroll
        for (int i = 0; i < 4; i++) {
            int f = tid + i * 128;
            int k = f >> 5;
            int c0 = (f & 31) * 4;
            const float* src = (c0 < 64) ? (Wl + (k0 + k) * 64 + c0)
                                         : (Wr + (k0 + k) * 64 + c0 - 64);
            *(float4*)&Ws[k][c0] = *(const float4*)src;
        }
        __syncthreads();
#pragma unroll
        for (int kk = 0; kk < 16; kk++) {
            float a[8], b[8];
            *(float4*)&a[0] = *(const float4*)&Xs[kk][ty * 8];
            *(float4*)&a[4] = *(const float4*)&Xs[kk][ty * 8 + 4];
            *(float4*)&b[0] = *(const float4*)&Ws[kk][tx * 8];
            *(float4*)&b[4] = *(const float4*)&Ws[kk][tx * 8 + 4];
#pragma unroll
            for (int i = 0; i < 8; i++)
#pragma unroll
                for (int j = 0; j < 8; j++) acc[i][j] += a[i] * b[j];
        }
        __syncthreads();
    }

    bool isP = (tx < 8);
    int c0 = (isP ? tx : tx - 8) * 8;
    float bias[8];
#pragma unroll
    for (int j = 0; j < 8; j++) bias[j] = isP ? 0.0f : bl[c0 + j];
    float* dstbuf = isP ? P : BASE;
#pragma unroll
    for (int i = 0; i < 8; i++) {
        int grow = row0 + ty * 8 + i;
        if (grow < N) {
            float4* o = (float4*)(dstbuf + grow * 64 + c0);
            o[0] = make_float4(acc[i][0] + bias[0], acc[i][1] + bias[1],
                               acc[i][2] + bias[2], acc[i][3] + bias[3]);
            o[1] = make_float4(acc[i][4] + bias[4], acc[i][5] + bias[5],
                               acc[i][6] + bias[6], acc[i][7] + bias[7]);
        }
    }
}

// h[i] = elu(base[i] + inv[i] * sum_{j in N(i)} p[j]) — one warp per node,
// lane handles 2 floats (float2). Unroll x4 with split accumulators for MLP.
// PROJ: additionally a[i] = h[i]@Wp_top + bp, b[i] = h[i]@Wp_bot via warp
// shuffle reduction (Wp staged in shared).
template <bool PROJ>
__global__ void gather_elu_kernel(const float* __restrict__ Wp,
                                  const float* __restrict__ bp) {
    __shared__ float Ws[512];
    if (PROJ) {
        for (int i = threadIdx.x; i < 512; i += blockDim.x) Ws[i] = Wp[i];
        __syncthreads();
    }
    int w = (blockIdx.x * blockDim.x + threadIdx.x) >> 5;
    if (w >= N_NODES) return;
    int lane = threadIdx.x & 31;
    int beg = g_row[w], end = g_row[w + 1];

    const float2* P = (const float2*)g_p;
    float ax0 = 0.f, ay0 = 0.f, ax1 = 0.f, ay1 = 0.f;
    int j = beg;
    for (; j + 3 < end; j += 4) {
        int s0 = g_csr[j],     s1 = g_csr[j + 1];
        int s2 = g_csr[j + 2], s3 = g_csr[j + 3];
        float2 v0 = P[s0 * 32 + lane];
        float2 v1 = P[s1 * 32 + lane];
        float2 v2 = P[s2 * 32 + lane];
        float2 v3 = P[s3 * 32 + lane];
        ax0 += v0.x + v1.x; ay0 += v0.y + v1.y;
        ax1 += v2.x + v3.x; ay1 += v2.y + v3.y;
    }
    for (; j < end; j++) {
        float2 v = P[g_csr[j] * 32 + lane];
        ax0 += v.x; ay0 += v.y;
    }
    float ax = ax0 + ax1, ay = ay0 + ay1;
    float inv = g_inv[w];
    float2 b = ((const float2*)g_base)[w * 32 + lane];
    float vx = b.x + inv * ax;
    float vy = b.y + inv * ay;
    vx = vx > 0.0f ? vx : expm1f(vx);
    vy = vy > 0.0f ? vy : expm1f(vy);
    ((float2*)g_h)[w * 32 + lane] = make_float2(vx, vy);

    if (PROJ) {
        int c0 = 2 * lane;
        float sa[4], sb[4];
#pragma unroll
        for (int o = 0; o < 4; o++) {
            sa[o] = vx * Ws[c0 * 4 + o]        + vy * Ws[(c0 + 1) * 4 + o];
            sb[o] = vx * Ws[(64 + c0) * 4 + o] + vy * Ws[(64 + c0 + 1) * 4 + o];
        }
#pragma unroll
        for (int off = 16; off > 0; off >>= 1) {
#pragma unroll
            for (int o = 0; o < 4; o++) {
                sa[o] += __shfl_xor_sync(0xffffffffu, sa[o], off);
                sb[o] += __shfl_xor_sync(0xffffffffu, sb[o], off);
            }
        }
        if (lane == 0) {
            g_a[w] = make_float4(sa[0] + bp[0], sa[1] + bp[1],
                                 sa[2] + bp[2], sa[3] + bp[3]);
            g_b[w] = make_float4(sb[0], sb[1], sb[2], sb[3]);
        }
    }
}

// out[e] = a[src] + b[dst]
__global__ void edge_out_kernel(float* __restrict__ out, int E) {
    int e = blockIdx.x * blockDim.x + threadIdx.x;
    if (e >= E) return;
    float4 a = g_a[g_src[e]];
    float4 b = g_b[g_dst[e]];
    ((float4*)out)[e] = make_float4(a.x + b.x, a.y + b.y, a.z + b.z, a.w + b.w);
}

extern "C" void kernel_launch(void* const* d_in, const int* in_sizes, int n_in,
                              void* d_out, int out_size) {
    const float* x   = (const float*)d_in[0];
    const int*   eiw = (const int*)d_in[1];   // raw words; dtype probed on device
    const float* Wl1 = (const float*)d_in[2];
    const float* bl1 = (const float*)d_in[3];
    const float* Wr1 = (const float*)d_in[4];
    const float* Wl2 = (const float*)d_in[5];
    const float* bl2 = (const float*)d_in[6];
    const float* Wr2 = (const float*)d_in[7];
    const float* Wl3 = (const float*)d_in[8];
    const float* bl3 = (const float*)d_in[9];
    const float* Wr3 = (const float*)d_in[10];
    const float* Wp  = (const float*)d_in[11];
    const float* bp  = (const float*)d_in[12];
    float* out = (float*)d_out;

    int E = in_sizes[1] / 2;
    if (E > E_MAX) E = E_MAX;

    float* d_p;    cudaGetSymbolAddress((void**)&d_p,    g_p);
    float* d_base; cudaGetSymbolAddress((void**)&d_base, g_base);
    float* d_h;    cudaGetSymbolAddress((void**)&d_h,    g_h);

    // Side stream + events for overlapping the CSR build with layer-1 GEMM.
    // Created once (outside any graph capture); event/wait nodes are legal
    // graph constructs and deterministic.
    static cudaStream_t s_csr = nullptr;
    static cudaEvent_t ev_fork = nullptr, ev_join = nullptr;
    if (!s_csr) {
        cudaStreamCreateWithFlags(&s_csr, cudaStreamNonBlocking);
        cudaEventCreateWithFlags(&ev_fork, cudaEventDisableTiming);
        cudaEventCreateWithFlags(&ev_join, cudaEventDisableTiming);
    }

    const int TB = 256;
    int gN    = (N_NODES + TB - 1) / TB;
    int gE    = (E + TB - 1) / TB;
    int gGath = (N_NODES * 32 + TB - 1) / TB;      // 1 warp per node
    int gGemm = (N_NODES + 63) / 64;               // 64 rows per block

    // Fork: CSR build on side stream, layer-1 GEMM on main stream.
    cudaEventRecord(ev_fork, 0);
    cudaStreamWaitEvent(s_csr, ev_fork, 0);

    zero_cnt_kernel<<<gN, TB, 0, s_csr>>>();
    convert_count_kernel<<<gE, TB, 0, s_csr>>>(eiw, E);
    scan_kernel<<<1, 1024, 0, s_csr>>>();
    fill_kernel<<<gE, TB, 0, s_csr>>>(E);
    cudaEventRecord(ev_join, s_csr);

    // Layer 1 (K=128) runs concurrently with the CSR build
    gemm2_kernel<<<gGemm, 128>>>(x, Wl1, Wr1, bl1, d_p, d_base, N_NODES, 128);

    // Join: gather needs CSR + GEMM1 results
    cudaStreamWaitEvent(0, ev_join, 0);
    gather_elu_kernel<false><<<gGath, TB>>>(nullptr, nullptr);

    // Layer 2 (K=64)
    gemm2_kernel<<<gGemm, 128>>>(d_h, Wl2, Wr2, bl2, d_p, d_base, N_NODES, 64);
    gather_elu_kernel<false><<<gGath, TB>>>(nullptr, nullptr);

    // Layer 3 (K=64) + fused edge-MLP projection
    gemm2_kernel<<<gGemm, 128>>>(d_h, Wl3, Wr3, bl3, d_p, d_base, N_NODES, 64);
    gather_elu_kernel<true><<<gGath, TB>>>(Wp, bp);

    // out[e] = a[src] + b[dst]
    edge_out_kernel<<<gE, TB>>>(out, E);
}

// round 9
// speedup vs baseline: 1.0725x; 1.0670x over previous
#include <cuda_runtime.h>
#include <math.h>

#define N_NODES 50000
#define E_MAX   800000
#define D_H 64

// Scratch (device globals -- no allocation allowed)
__device__ float g_p[N_NODES * D_H];      // x @ Wl
__device__ float g_base[N_NODES * D_H];   // x @ Wr + bl
__device__ float g_h[N_NODES * D_H];      // elu(...) -> next layer input
__device__ int   g_cnt[N_NODES];
__device__ float g_inv[N_NODES];
__device__ int   g_row[N_NODES + 1];      // CSR row offsets (by dst)
__device__ int   g_cursor[N_NODES];
__device__ int   g_csr[E_MAX];            // src indices grouped by dst
__device__ int   g_src[E_MAX];
__device__ int   g_dst[E_MAX];
__device__ float4 g_a[N_NODES];           // h @ Wp_top + bp
__device__ float4 g_b[N_NODES];           // h @ Wp_bot

__global__ void zero_cnt_kernel() {
    int i = blockIdx.x * blockDim.x + threadIdx.x;
    if (i < N_NODES) g_cnt[i] = 0;
}

// decode src/dst (+ count degrees) in one pass. int64-vs-int32 detection is
// done per block from the first 128 words (all L2-broadcast): for int64
// indices < 2^31 every odd word is 0; for 64 random int32 indices it isn't.
__global__ void convert_count_kernel(const int* __restrict__ w, int E) {
    __shared__ int is64_s;
    if (threadIdx.x == 0) {
        int z = 1;
        for (int i = 1; i < 129; i += 2)
            if (w[i] != 0) { z = 0; break; }
        is64_s = z;
    }
    __syncthreads();
    int is64 = is64_s;
    int e = blockIdx.x * blockDim.x + threadIdx.x;
    if (e >= E) return;
    int s, d;
    if (is64) { s = w[2 * e]; d = w[2 * (E + e)]; }
    else      { s = w[e];     d = w[E + e]; }
    g_src[e] = s;
    g_dst[e] = d;
    atomicAdd(&g_cnt[d], 1);
}

// Single block, 1024 threads: exclusive scan of g_cnt -> g_row, g_cursor, g_inv
__global__ void scan_kernel() {
    __shared__ int sums[1024];
    int t = threadIdx.x;
    const int CH = (N_NODES + 1023) / 1024;
    int begin = t * CH;
    int end = begin + CH; if (end > N_NODES) end = N_NODES;
    int s = 0;
    for (int i = begin; i < end; i++) s += g_cnt[i];
    sums[t] = s;
    __syncthreads();
    for (int off = 1; off < 1024; off <<= 1) {
        int v = (t >= off) ? sums[t - off] : 0;
        __syncthreads();
        sums[t] += v;
        __syncthreads();
    }
    int run = (t == 0) ? 0 : sums[t - 1];
    for (int i = begin; i < end; i++) {
        g_row[i] = run;
        g_cursor[i] = run;
        int c = g_cnt[i];
        run += c;
        g_inv[i] = 1.0f / (float)(c > 1 ? c : 1);
    }
    if (t == 1023) g_row[N_NODES] = run;
}

__global__ void fill_kernel(int E) {
    int e = blockIdx.x * blockDim.x + threadIdx.x;
    if (e < E) {
        int pos = atomicAdd(&g_cursor[g_dst[e]], 1);
        g_csr[pos] = g_src[e];
    }
}

// Fused dual GEMM: P = X @ Wl ; BASE = X @ Wr + bl.  (R5 version, proven)
// Block computes 64 rows x 128 combined cols (0-63 -> P, 64-127 -> BASE).
// 128 threads, 8x8 register tile each: 4x LDS.128 per k feeds 64 FMA.
__global__ void __launch_bounds__(128) gemm2_kernel(
        const float* __restrict__ X,
        const float* __restrict__ Wl, const float* __restrict__ Wr,
        const float* __restrict__ bl,
        float* __restrict__ P, float* __restrict__ BASE,
        int N, int K) {
    __shared__ float Xs[16][64];
    __shared__ float Ws[16][128];
    int tid = threadIdx.x;
    int tx = tid & 15;       // col group (8 cols)
    int ty = tid >> 4;       // row group (8 rows)
    int row0 = blockIdx.x * 64;

    float acc[8][8];
#pragma unroll
    for (int i = 0; i < 8; i++)
#pragma unroll
        for (int j = 0; j < 8; j++) acc[i][j] = 0.0f;

    for (int k0 = 0; k0 < K; k0 += 16) {
#pragma unroll
        for (int i = 0; i < 2; i++) {
            int f = tid + i * 128;
            int r = f >> 2;
            int kq = (f & 3) * 4;
            int grow = row0 + r;
            float4 v = make_float4(0.f, 0.f, 0.f, 0.f);
            if (grow < N) v = *(const float4*)(X + (long)grow * K + k0 + kq);
            Xs[kq + 0][r] = v.x; Xs[kq + 1][r] = v.y;
            Xs[kq + 2][r] = v.z; Xs[kq + 3][r] = v.w;
        }
#pragma unroll
        for (int i = 0; i < 4; i++) {
            int f = tid + i * 128;
            int k = f >> 5;
            int c0 = (f & 31) * 4;
            const float* src = (c0 < 64) ? (Wl + (k0 + k) * 64 + c0)
                                         : (Wr + (k0 + k) * 64 + c0 - 64);
            *(float4*)&Ws[k][c0] = *(const float4*)src;
        }
        __syncthreads();
#pragma unroll
        for (int kk = 0; kk < 16; kk++) {
            float a[8], b[8];
            *(float4*)&a[0] = *(const float4*)&Xs[kk][ty * 8];
            *(float4*)&a[4] = *(const float4*)&Xs[kk][ty * 8 + 4];
            *(float4*)&b[0] = *(const float4*)&Ws[kk][tx * 8];
            *(float4*)&b[4] = *(const float4*)&Ws[kk][tx * 8 + 4];
#pragma unroll
            for (int i = 0; i < 8; i++)
#pragma unroll
                for (int j = 0; j < 8; j++) acc[i][j] += a[i] * b[j];
        }
        __syncthreads();
    }

    bool isP = (tx < 8);
    int c0 = (isP ? tx : tx - 8) * 8;
    float bias[8];
#pragma unroll
    for (int j = 0; j < 8; j++) bias[j] = isP ? 0.0f : bl[c0 + j];
    float* dstbuf = isP ? P : BASE;
#pragma unroll
    for (int i = 0; i < 8; i++) {
        int grow = row0 + ty * 8 + i;
        if (grow < N) {
            float4* o = (float4*)(dstbuf + grow * 64 + c0);
            o[0] = make_float4(acc[i][0] + bias[0], acc[i][1] + bias[1],
                               acc[i][2] + bias[2], acc[i][3] + bias[3]);
            o[1] = make_float4(acc[i][4] + bias[4], acc[i][5] + bias[5],
                               acc[i][6] + bias[6], acc[i][7] + bias[7]);
        }
    }
}

// h[i] = elu(base[i] + inv[i] * sum_{j in N(i)} p[j]) — one warp per node,
// lane handles 2 floats (float2), unroll x2 (R5 version, proven).
// PROJ: additionally a[i] = h[i]@Wp_top + bp, b[i] = h[i]@Wp_bot via warp
// shuffle reduction (Wp staged in shared).
template <bool PROJ>
__global__ void gather_elu_kernel(const float* __restrict__ Wp,
                                  const float* __restrict__ bp) {
    __shared__ float Ws[512];
    if (PROJ) {
        for (int i = threadIdx.x; i < 512; i += blockDim.x) Ws[i] = Wp[i];
        __syncthreads();
    }
    int w = (blockIdx.x * blockDim.x + threadIdx.x) >> 5;
    if (w >= N_NODES) return;
    int lane = threadIdx.x & 31;
    int beg = g_row[w], end = g_row[w + 1];

    const float2* P = (const float2*)g_p;
    float ax = 0.0f, ay = 0.0f;
    int j = beg;
    for (; j + 1 < end; j += 2) {
        int s0 = g_csr[j], s1 = g_csr[j + 1];
        float2 v0 = P[s0 * 32 + lane];
        float2 v1 = P[s1 * 32 + lane];
        ax += v0.x + v1.x;
        ay += v0.y + v1.y;
    }
    if (j < end) {
        float2 v = P[g_csr[j] * 32 + lane];
        ax += v.x; ay += v.y;
    }
    float inv = g_inv[w];
    float2 b = ((const float2*)g_base)[w * 32 + lane];
    float vx = b.x + inv * ax;
    float vy = b.y + inv * ay;
    vx = vx > 0.0f ? vx : expm1f(vx);
    vy = vy > 0.0f ? vy : expm1f(vy);
    ((float2*)g_h)[w * 32 + lane] = make_float2(vx, vy);

    if (PROJ) {
        int c0 = 2 * lane;
        float sa[4], sb[4];
#pragma unroll
        for (int o = 0; o < 4; o++) {
            sa[o] = vx * Ws[c0 * 4 + o]        + vy * Ws[(c0 + 1) * 4 + o];
            sb[o] = vx * Ws[(64 + c0) * 4 + o] + vy * Ws[(64 + c0 + 1) * 4 + o];
        }
#pragma unroll
        for (int off = 16; off > 0; off >>= 1) {
#pragma unroll
            for (int o = 0; o < 4; o++) {
                sa[o] += __shfl_xor_sync(0xffffffffu, sa[o], off);
                sb[o] += __shfl_xor_sync(0xffffffffu, sb[o], off);
            }
        }
        if (lane == 0) {
            g_a[w] = make_float4(sa[0] + bp[0], sa[1] + bp[1],
                                 sa[2] + bp[2], sa[3] + bp[3]);
            g_b[w] = make_float4(sb[0], sb[1], sb[2], sb[3]);
        }
    }
}

// out[e] = a[src] + b[dst]
__global__ void edge_out_kernel(float* __restrict__ out, int E) {
    int e = blockIdx.x * blockDim.x + threadIdx.x;
    if (e >= E) return;
    float4 a = g_a[g_src[e]];
    float4 b = g_b[g_dst[e]];
    ((float4*)out)[e] = make_float4(a.x + b.x, a.y + b.y, a.z + b.z, a.w + b.w);
}

extern "C" void kernel_launch(void* const* d_in, const int* in_sizes, int n_in,
                              void* d_out, int out_size) {
    const float* x   = (const float*)d_in[0];
    const int*   eiw = (const int*)d_in[1];   // raw words; dtype probed on device
    const float* Wl1 = (const float*)d_in[2];
    const float* bl1 = (const float*)d_in[3];
    const float* Wr1 = (const float*)d_in[4];
    const float* Wl2 = (const float*)d_in[5];
    const float* bl2 = (const float*)d_in[6];
    const float* Wr2 = (const float*)d_in[7];
    const float* Wl3 = (const float*)d_in[8];
    const float* bl3 = (const float*)d_in[9];
    const float* Wr3 = (const float*)d_in[10];
    const float* Wp  = (const float*)d_in[11];
    const float* bp  = (const float*)d_in[12];
    float* out = (float*)d_out;

    int E = in_sizes[1] / 2;
    if (E > E_MAX) E = E_MAX;

    float* d_p;    cudaGetSymbolAddress((void**)&d_p,    g_p);
    float* d_base; cudaGetSymbolAddress((void**)&d_base, g_base);
    float* d_h;    cudaGetSymbolAddress((void**)&d_h,    g_h);

    // Side stream + events: overlap the CSR build (L2/atomic-bound) with the
    // layer-1 GEMM (FMA-bound). Created once, reused; fork/join via events
    // is graph-legal and deterministic.
    static cudaStream_t s_csr = nullptr;
    static cudaEvent_t ev_fork = nullptr, ev_join = nullptr;
    if (!s_csr) {
        cudaStreamCreateWithFlags(&s_csr, cudaStreamNonBlocking);
        cudaEventCreateWithFlags(&ev_fork, cudaEventDisableTiming);
        cudaEventCreateWithFlags(&ev_join, cudaEventDisableTiming);
    }

    const int TB = 256;
    int gN    = (N_NODES + TB - 1) / TB;
    int gE    = (E + TB - 1) / TB;
    int gGath = (N_NODES * 32 + TB - 1) / TB;      // 1 warp per node
    int gGemm = (N_NODES + 63) / 64;               // 64 rows per block

    // Fork: CSR build on side stream, layer-1 GEMM on main stream.
    cudaEventRecord(ev_fork, 0);
    cudaStreamWaitEvent(s_csr, ev_fork, 0);

    zero_cnt_kernel<<<gN, TB, 0, s_csr>>>();
    convert_count_kernel<<<gE, TB, 0, s_csr>>>(eiw, E);
    scan_kernel<<<1, 1024, 0, s_csr>>>();
    fill_kernel<<<gE, TB, 0, s_csr>>>(E);
    cudaEventRecord(ev_join, s_csr);

    // Layer 1 (K=128) runs concurrently with the CSR build
    gemm2_kernel<<<gGemm, 128>>>(x, Wl1, Wr1, bl1, d_p, d_base, N_NODES, 128);

    // Join: gather needs CSR + GEMM1 results
    cudaStreamWaitEvent(0, ev_join, 0);
    gather_elu_kernel<false><<<gGath, TB>>>(nullptr, nullptr);

    // Layer 2 (K=64)
    gemm2_kernel<<<gGemm, 128>>>(d_h, Wl2, Wr2, bl2, d_p, d_base, N_NODES, 64);
    gather_elu_kernel<false><<<gGath, TB>>>(nullptr, nullptr);

    // Layer 3 (K=64) + fused edge-MLP projection
    gemm2_kernel<<<gGemm, 128>>>(d_h, Wl3, Wr3, bl3, d_p, d_base, N_NODES, 64);
    gather_elu_kernel<true><<<gGath, TB>>>(Wp, bp);

    // out[e] = a[src] + b[dst]
    edge_out_kernel<<<gE, TB>>>(out, E);
}

// round 11
// speedup vs baseline: 1.0867x; 1.0132x over previous
#include <cuda_runtime.h>
#include <math.h>

#define N_NODES 50000
#define E_MAX   800000
#define D_H 64
#define KC 16   // K-chunk for tf32 GEMM

// Scratch (device globals -- no allocation allowed)
__device__ float g_p[N_NODES * D_H];      // x @ Wl
__device__ float g_base[N_NODES * D_H];   // x @ Wr + bl
__device__ float g_h[N_NODES * D_H];      // elu(...) -> next layer input
__device__ int   g_cnt[N_NODES];
__device__ float g_inv[N_NODES];
__device__ int   g_row[N_NODES + 1];      // CSR row offsets (by dst)
__device__ int   g_cursor[N_NODES];
__device__ int   g_csr[E_MAX];            // src indices grouped by dst
__device__ int   g_src[E_MAX];
__device__ int   g_dst[E_MAX];
__device__ float4 g_a[N_NODES];           // h @ Wp_top + bp
__device__ float4 g_b[N_NODES];           // h @ Wp_bot

__device__ __forceinline__ unsigned f2tf32(float x) {
    unsigned r;
    asm("cvt.rna.tf32.f32 %0, %1;" : "=r"(r) : "f"(x));
    return r;
}

__device__ __forceinline__ void mma_tf32(float c[4],
        unsigned a0, unsigned a1, unsigned a2, unsigned a3,
        unsigned b0, unsigned b1) {
    asm volatile(
        "mma.sync.aligned.m16n8k8.row.col.f32.tf32.tf32.f32 "
        "{%0,%1,%2,%3}, {%4,%5,%6,%7}, {%8,%9}, {%0,%1,%2,%3};"
        : "+f"(c[0]), "+f"(c[1]), "+f"(c[2]), "+f"(c[3])
        : "r"(a0), "r"(a1), "r"(a2), "r"(a3), "r"(b0), "r"(b1));
}

__global__ void zero_cnt_kernel() {
    int i = blockIdx.x * blockDim.x + threadIdx.x;
    if (i < N_NODES) g_cnt[i] = 0;
}

// decode src/dst (+ count degrees) in one pass. int64-vs-int32 detection is
// done per block from the first 128 words (all L2-broadcast): for int64
// indices < 2^31 every odd word is 0; for 64 random int32 indices it isn't.
__global__ void convert_count_kernel(const int* __restrict__ w, int E) {
    __shared__ int is64_s;
    if (threadIdx.x == 0) {
        int z = 1;
        for (int i = 1; i < 129; i += 2)
            if (w[i] != 0) { z = 0; break; }
        is64_s = z;
    }
    __syncthreads();
    int is64 = is64_s;
    int e = blockIdx.x * blockDim.x + threadIdx.x;
    if (e >= E) return;
    int s, d;
    if (is64) { s = w[2 * e]; d = w[2 * (E + e)]; }
    else      { s = w[e];     d = w[E + e]; }
    g_src[e] = s;
    g_dst[e] = d;
    atomicAdd(&g_cnt[d], 1);
}

// Single block, 1024 threads: exclusive scan of g_cnt -> g_row, g_cursor, g_inv
__global__ void scan_kernel() {
    __shared__ int sums[1024];
    int t = threadIdx.x;
    const int CH = (N_NODES + 1023) / 1024;
    int begin = t * CH;
    int end = begin + CH; if (end > N_NODES) end = N_NODES;
    int s = 0;
    for (int i = begin; i < end; i++) s += g_cnt[i];
    sums[t] = s;
    __syncthreads();
    for (int off = 1; off < 1024; off <<= 1) {
        int v = (t >= off) ? sums[t - off] : 0;
        __syncthreads();
        sums[t] += v;
        __syncthreads();
    }
    int run = (t == 0) ? 0 : sums[t - 1];
    for (int i = begin; i < end; i++) {
        g_row[i] = run;
        g_cursor[i] = run;
        int c = g_cnt[i];
        run += c;
        g_inv[i] = 1.0f / (float)(c > 1 ? c : 1);
    }
    if (t == 1023) g_row[N_NODES] = run;
}

__global__ void fill_kernel(int E) {
    int e = blockIdx.x * blockDim.x + threadIdx.x;
    if (e < E) {
        int pos = atomicAdd(&g_cursor[g_dst[e]], 1);
        g_csr[pos] = g_src[e];
    }
}

// Fused dual GEMM on tensor cores (tf32, 3-term split precision):
//   P = X @ Wl ; BASE = X @ Wr + bl.
// Block: 256 threads (8 warps), output 64 rows x 128 combined cols
// (0-63 -> P, 64-127 -> BASE). Warp w: rows (w>>1)*16.., cols (w&1)*64..
// Each fp32 operand splits x = hi + lo (tf32 + residual); product computed
// as hi*hi + hi*lo + lo*hi (err ~2^-21). Shared strides 72/136 are ≡8 mod 32
// so all fragment LDS are bank-conflict-free.
__global__ void __launch_bounds__(256) gemm2_kernel(
        const float* __restrict__ X,
        const float* __restrict__ Wl, const float* __restrict__ Wr,
        const float* __restrict__ bl,
        float* __restrict__ P, float* __restrict__ BASE,
        int N, int K) {
    __shared__ float Xh[KC][72], Xlo[KC][72];     // [k][row], rows 0..63
    __shared__ float Wh[KC][136], Wlo[KC][136];   // [k][combined col 0..127]
    int tid  = threadIdx.x;
    int warp = tid >> 5, lane = tid & 31;
    int gid  = lane >> 2, tig = lane & 3;
    int rg   = warp >> 1;            // row group: rows rg*16..rg*16+15
    int chf  = warp & 1;             // col half:  cols chf*64..chf*64+63
    int row0 = blockIdx.x * 64;

    float acc[8][4];
#pragma unroll
    for (int j = 0; j < 8; j++)
#pragma unroll
        for (int q = 0; q < 4; q++) acc[j][q] = 0.0f;

    for (int k0 = 0; k0 < K; k0 += KC) {
        // stage X tile: 64 rows x KC k, transposed + hi/lo split
        {
            int r  = tid >> 2;           // 0..63
            int kq = (tid & 3) * 4;      // 0,4,8,12
            int grow = row0 + r;
            float4 v = make_float4(0.f, 0.f, 0.f, 0.f);
            if (grow < N) v = *(const float4*)(X + (long)grow * K + k0 + kq);
            float xv[4] = {v.x, v.y, v.z, v.w};
#pragma unroll
            for (int u = 0; u < 4; u++) {
                unsigned h = f2tf32(xv[u]);
                float hf = __uint_as_float(h);
                Xh[kq + u][r]  = hf;
                Xlo[kq + u][r] = __uint_as_float(f2tf32(xv[u] - hf));
            }
        }
        // stage combined W tile: KC k x 128 cols, hi/lo split
#pragma unroll
        for (int i = 0; i < 2; i++) {
            int f  = tid + i * 256;      // 0..511 float4 slots
            int k  = f >> 5;             // 0..15
            int c0 = (f & 31) * 4;       // 0..124
            const float* src = (c0 < 64) ? (Wl + (k0 + k) * 64 + c0)
                                         : (Wr + (k0 + k) * 64 + c0 - 64);
            float4 v = *(const float4*)src;
            float wv[4] = {v.x, v.y, v.z, v.w};
#pragma unroll
            for (int u = 0; u < 4; u++) {
                unsigned h = f2tf32(wv[u]);
                float hf = __uint_as_float(h);
                Wh[k][c0 + u]  = hf;
                Wlo[k][c0 + u] = __uint_as_float(f2tf32(wv[u] - hf));
            }
        }
        __syncthreads();

#pragma unroll
        for (int ks = 0; ks < KC; ks += 8) {
            int arow = rg * 16 + gid;
            unsigned ah[4], al[4];
            ah[0] = __float_as_uint(Xh[ks + tig][arow]);
            ah[1] = __float_as_uint(Xh[ks + tig][arow + 8]);
            ah[2] = __float_as_uint(Xh[ks + tig + 4][arow]);
            ah[3] = __float_as_uint(Xh[ks + tig + 4][arow + 8]);
            al[0] = __float_as_uint(Xlo[ks + tig][arow]);
            al[1] = __float_as_uint(Xlo[ks + tig][arow + 8]);
            al[2] = __float_as_uint(Xlo[ks + tig + 4][arow]);
            al[3] = __float_as_uint(Xlo[ks + tig + 4][arow + 8]);
#pragma unroll
            for (int j = 0; j < 8; j++) {
                int bn = chf * 64 + j * 8 + gid;
                unsigned bh0 = __float_as_uint(Wh[ks + tig][bn]);
                unsigned bh1 = __float_as_uint(Wh[ks + tig + 4][bn]);
                unsigned bl0 = __float_as_uint(Wlo[ks + tig][bn]);
                unsigned bl1 = __float_as_uint(Wlo[ks + tig + 4][bn]);
                mma_tf32(acc[j], ah[0], ah[1], ah[2], ah[3], bh0, bh1);
                mma_tf32(acc[j], ah[0], ah[1], ah[2], ah[3], bl0, bl1);
                mma_tf32(acc[j], al[0], al[1], al[2], al[3], bh0, bh1);
            }
        }
        __syncthreads();
    }

    // epilogue: c0/c1 -> (row, col 2*tig/2*tig+1), c2/c3 -> row+8
#pragma unroll
    for (int j = 0; j < 8; j++) {
        int c = chf * 64 + j * 8 + 2 * tig;   // combined col of acc[j][0]
        bool isP = (c < 64);
        float* buf = isP ? P : BASE;
        int cc = isP ? c : c - 64;
        float b0v = isP ? 0.0f : bl[cc];
        float b1v = isP ? 0.0f : bl[cc + 1];
        int r1 = row0 + rg * 16 + gid;
        if (r1 < N)
            *(float2*)(buf + r1 * 64 + cc) =
                make_float2(acc[j][0] + b0v, acc[j][1] + b1v);
        int r2 = r1 + 8;
        if (r2 < N)
            *(float2*)(buf + r2 * 64 + cc) =
                make_float2(acc[j][2] + b0v, acc[j][3] + b1v);
    }
}

// h[i] = elu(base[i] + inv[i] * sum_{j in N(i)} p[j]) — one warp per node,
// lane handles 2 floats (float2), unroll x2 (R5 version, proven).
// PROJ: additionally a[i] = h[i]@Wp_top + bp, b[i] = h[i]@Wp_bot via warp
// shuffle reduction (Wp staged in shared).
template <bool PROJ>
__global__ void gather_elu_kernel(const float* __restrict__ Wp,
                                  const float* __restrict__ bp) {
    __shared__ float Ws[512];
    if (PROJ) {
        for (int i = threadIdx.x; i < 512; i += blockDim.x) Ws[i] = Wp[i];
        __syncthreads();
    }
    int w = (blockIdx.x * blockDim.x + threadIdx.x) >> 5;
    if (w >= N_NODES) return;
    int lane = threadIdx.x & 31;
    int beg = g_row[w], end = g_row[w + 1];

    const float2* P = (const float2*)g_p;
    float ax = 0.0f, ay = 0.0f;
    int j = beg;
    for (; j + 1 < end; j += 2) {
        int s0 = g_csr[j], s1 = g_csr[j + 1];
        float2 v0 = P[s0 * 32 + lane];
        float2 v1 = P[s1 * 32 + lane];
        ax += v0.x + v1.x;
        ay += v0.y + v1.y;
    }
    if (j < end) {
        float2 v = P[g_csr[j] * 32 + lane];
        ax += v.x; ay += v.y;
    }
    float inv = g_inv[w];
    float2 b = ((const float2*)g_base)[w * 32 + lane];
    float vx = b.x + inv * ax;
    float vy = b.y + inv * ay;
    vx = vx > 0.0f ? vx : expm1f(vx);
    vy = vy > 0.0f ? vy : expm1f(vy);
    ((float2*)g_h)[w * 32 + lane] = make_float2(vx, vy);

    if (PROJ) {
        int c0 = 2 * lane;
        float sa[4], sb[4];
#pragma unroll
        for (int o = 0; o < 4; o++) {
            sa[o] = vx * Ws[c0 * 4 + o]        + vy * Ws[(c0 + 1) * 4 + o];
            sb[o] = vx * Ws[(64 + c0) * 4 + o] + vy * Ws[(64 + c0 + 1) * 4 + o];
        }
#pragma unroll
        for (int off = 16; off > 0; off >>= 1) {
#pragma unroll
            for (int o = 0; o < 4; o++) {
                sa[o] += __shfl_xor_sync(0xffffffffu, sa[o], off);
                sb[o] += __shfl_xor_sync(0xffffffffu, sb[o], off);
            }
        }
        if (lane == 0) {
            g_a[w] = make_float4(sa[0] + bp[0], sa[1] + bp[1],
                                 sa[2] + bp[2], sa[3] + bp[3]);
            g_b[w] = make_float4(sb[0], sb[1], sb[2], sb[3]);
        }
    }
}

// out[e] = a[src] + b[dst]
__global__ void edge_out_kernel(float* __restrict__ out, int E) {
    int e = blockIdx.x * blockDim.x + threadIdx.x;
    if (e >= E) return;
    float4 a = g_a[g_src[e]];
    float4 b = g_b[g_dst[e]];
    ((float4*)out)[e] = make_float4(a.x + b.x, a.y + b.y, a.z + b.z, a.w + b.w);
}

extern "C" void kernel_launch(void* const* d_in, const int* in_sizes, int n_in,
                              void* d_out, int out_size) {
    const float* x   = (const float*)d_in[0];
    const int*   eiw = (const int*)d_in[1];   // raw words; dtype probed on device
    const float* Wl1 = (const float*)d_in[2];
    const float* bl1 = (const float*)d_in[3];
    const float* Wr1 = (const float*)d_in[4];
    const float* Wl2 = (const float*)d_in[5];
    const float* bl2 = (const float*)d_in[6];
    const float* Wr2 = (const float*)d_in[7];
    const float* Wl3 = (const float*)d_in[8];
    const float* bl3 = (const float*)d_in[9];
    const float* Wr3 = (const float*)d_in[10];
    const float* Wp  = (const float*)d_in[11];
    const float* bp  = (const float*)d_in[12];
    float* out = (float*)d_out;

    int E = in_sizes[1] / 2;
    if (E > E_MAX) E = E_MAX;

    float* d_p;    cudaGetSymbolAddress((void**)&d_p,    g_p);
    float* d_base; cudaGetSymbolAddress((void**)&d_base, g_base);
    float* d_h;    cudaGetSymbolAddress((void**)&d_h,    g_h);

    // Side stream + events: overlap the CSR build (L2/atomic-bound) with the
    // layer-1 GEMM (tensor-bound). Created once, reused; fork/join via events
    // is graph-legal and deterministic.
    static cudaStream_t s_csr = nullptr;
    static cudaEvent_t ev_fork = nullptr, ev_join = nullptr;
    if (!s_csr) {
        cudaStreamCreateWithFlags(&s_csr, cudaStreamNonBlocking);
        cudaEventCreateWithFlags(&ev_fork, cudaEventDisableTiming);
        cudaEventCreateWithFlags(&ev_join, cudaEventDisableTiming);
    }

    const int TB = 256;
    int gN    = (N_NODES + TB - 1) / TB;
    int gE    = (E + TB - 1) / TB;
    int gGath = (N_NODES * 32 + TB - 1) / TB;      // 1 warp per node
    int gGemm = (N_NODES + 63) / 64;               // 64 rows per block

    // Fork: CSR build on side stream, layer-1 GEMM on main stream.
    cudaEventRecord(ev_fork, 0);
    cudaStreamWaitEvent(s_csr, ev_fork, 0);

    zero_cnt_kernel<<<gN, TB, 0, s_csr>>>();
    convert_count_kernel<<<gE, TB, 0, s_csr>>>(eiw, E);
    scan_kernel<<<1, 1024, 0, s_csr>>>();
    fill_kernel<<<gE, TB, 0, s_csr>>>(E);
    cudaEventRecord(ev_join, s_csr);

    // Layer 1 (K=128) runs concurrently with the CSR build
    gemm2_kernel<<<gGemm, 256>>>(x, Wl1, Wr1, bl1, d_p, d_base, N_NODES, 128);

    // Join: gather needs CSR + GEMM1 results
    cudaStreamWaitEvent(0, ev_join, 0);
    gather_elu_kernel<false><<<gGath, TB>>>(nullptr, nullptr);

    // Layer 2 (K=64)
    gemm2_kernel<<<gGemm, 256>>>(d_h, Wl2, Wr2, bl2, d_p, d_base, N_NODES, 64);
    gather_elu_kernel<false><<<gGath, TB>>>(nullptr, nullptr);

    // Layer 3 (K=64) + fused edge-MLP projection
    gemm2_kernel<<<gGemm, 256>>>(d_h, Wl3, Wr3, bl3, d_p, d_base, N_NODES, 64);
    gather_elu_kernel<true><<<gGath, TB>>>(Wp, bp);

    // out[e] = a[src] + b[dst]
    edge_out_kernel<<<gE, TB>>>(out, E);
}